// round 11
// baseline (speedup 1.0000x reference)
#include <cuda_runtime.h>
#include <cuda_bf16.h>

#define B_  16
#define N_  512
#define E_  32
#define HD  64

// Scratch: A[b][k][n] = H[b,n,:] @ W1[:32, k]
//          Bm[b][k][n] = H[b,n,:] @ W1[32:, k] + b1[k]
__device__ float g_A[B_ * HD * N_];
__device__ float g_Bm[B_ * HD * N_];

// Monotonic grid-barrier counter (never reset; each call adds exactly 576,
// calls are stream-serialized -> replay-safe, no sense flag).
__device__ unsigned long long g_bar = 0ULL;

// ---------------------------------------------------------------------------
// smem union: precompute scratch overlaps the pair tiles (phases separated
// by the grid barrier). pair = 48KB, pre = 12.4KB. 4 blocks/SM.
// ---------------------------------------------------------------------------
struct SmemPre  { float sW[E_ * 32]; float sH[64 * 33]; };
struct SmemPair { unsigned long long As_dup[HD * 64];      // 32 KB  [k][i] (a,a)
                  unsigned long long Bs2[HD * 32]; };      // 16 KB  [k][pos] (bj,bj+1)
union  SmemU    { SmemPre pre; SmemPair pair; };

__device__ __forceinline__ unsigned long long dup_f32(float x)
{
    unsigned long long d;
    asm("mov.b64 %0, {%1, %1};" : "=l"(d) : "f"(x));
    return d;
}

// packed f32x2 inner step (R2-proven minimum-issue form)
__device__ __forceinline__ void pair_step(unsigned long long& acc,
                                          unsigned long long a2,
                                          unsigned long long b2,
                                          unsigned long long w2)
{
    asm("{\n\t"
        ".reg .f32 lo, hi;\n\t"
        ".reg .b64 t, r;\n\t"
        "add.rn.f32x2 t, %1, %2;\n\t"
        "mov.b64 {lo, hi}, t;\n\t"
        "max.f32 lo, lo, 0f00000000;\n\t"
        "max.f32 hi, hi, 0f00000000;\n\t"
        "mov.b64 r, {lo, hi};\n\t"
        "fma.rn.f32x2 %0, r, %3, %0;\n\t"
        "}"
        : "+l"(acc) : "l"(a2), "l"(b2), "l"(w2));
}

// ---------------------------------------------------------------------------
// Fused kernel: precompute (blocks 0..511) -> grid barrier -> pair MLP (all).
// ---------------------------------------------------------------------------
__global__ void __launch_bounds__(256, 4) fused_kernel(
    const float* __restrict__ H,
    const float* __restrict__ W1,
    const float* __restrict__ b1,
    const float* __restrict__ W2,
    const float* __restrict__ b2g,
    float* __restrict__ out)
{
    __shared__ SmemU sm;
    __shared__ unsigned long long sw2d[HD];
    __shared__ float sb2;

    int tid = threadIdx.x;
    int bid = blockIdx.x;

    // weights prolog (disjoint smem region)
    if (tid < HD) sw2d[tid] = dup_f32(W2[tid]);
    if (tid == 0) sb2 = b2g[0];

    // ---- phase 1: precompute chunk (512 chunks over blocks 0..511) ----
    if (bid < 512) {
        int khalf  = bid & 1;
        int which  = (bid >> 1) & 1;
        int nChunk = (bid >> 2) & 7;
        int pb     = bid >> 5;

        const float* Wsrc = W1 + which * E_ * HD + khalf * 32;
        #pragma unroll
        for (int p = tid; p < E_ * 32; p += 256) {
            int r = p >> 5, c = p & 31;
            sm.pre.sW[p] = Wsrc[r * HD + c];
        }
        int nBase = pb * N_ + nChunk * 64;
        #pragma unroll
        for (int p = tid; p < 64 * E_; p += 256) {
            int r = p >> 5, c = p & 31;
            sm.pre.sH[r * 33 + c] = H[nBase * E_ + p];
        }
        __syncthreads();

        int nL   = tid & 63;
        int kOff = (tid >> 6) * 8;

        float h[E_];
        #pragma unroll
        for (int e = 0; e < E_; e++) h[e] = sm.pre.sH[nL * 33 + e];

        float* dst = which ? g_Bm : g_A;
        #pragma unroll
        for (int kk = 0; kk < 8; kk++) {
            int kq = kOff + kk;
            int k  = khalf * 32 + kq;
            float acc = which ? b1[k] : 0.0f;
            #pragma unroll
            for (int e = 0; e < E_; e++)
                acc = fmaf(h[e], sm.pre.sW[e * 32 + kq], acc);
            dst[(pb * HD + k) * N_ + nChunk * 64 + nL] = acc;
        }
    }

    // ---- grid barrier (all 576 blocks co-resident: 4/SM x 148 = 592) ----
    __syncthreads();
    if (tid == 0) {
        __threadfence();
        unsigned long long old = atomicAdd(&g_bar, 1ULL);
        unsigned long long target = (old / 576ULL + 1ULL) * 576ULL;
        while (*(volatile unsigned long long*)&g_bar < target) { }
        __threadfence();
    }
    __syncthreads();

    // ---- phase 2: pair MLP, EXACT R2 loop (44 issues/k, fastest measured) --
    int b = bid & 15;
    int t = bid >> 4;
    int ti = 0;
    while (t >= (8 - ti)) { t -= (8 - ti); ti++; }
    int tj = ti + t;    // ti <= tj

    // Fill As_dup: LDG.128 + duplicate + 2x STS.128 per float4
    const float4* Ag4 = reinterpret_cast<const float4*>(g_A + (size_t)b * HD * N_ + ti * 64);
    #pragma unroll
    for (int p = 0; p < 4; p++) {
        int idx = tid + p * 256;          // 0..1023 float4 slots
        int k = idx >> 4, q = idx & 15;
        float4 v = Ag4[k * (N_ / 4) + q];
        ulonglong2* dst = reinterpret_cast<ulonglong2*>(&sm.pair.As_dup[(k << 6) + (q << 2)]);
        dst[0] = make_ulonglong2(dup_f32(v.x), dup_f32(v.y));
        dst[1] = make_ulonglong2(dup_f32(v.z), dup_f32(v.w));
    }
    // Fill Bs2: adjacent-j pairs, interleaved: pair jp -> (jp&1)*16 + (jp>>1)
    const float2* Bg = reinterpret_cast<const float2*>(g_Bm + (size_t)b * HD * N_ + tj * 64);
    #pragma unroll
    for (int p = 0; p < 8; p++) {
        int idx = tid + p * 256;          // 0..2047
        int k = idx >> 5, jp = idx & 31;
        float2 v = Bg[k * (N_ / 2) + jp];
        int pos = ((jp & 1) << 4) | (jp >> 1);
        sm.pair.Bs2[(k << 5) + pos] = *reinterpret_cast<unsigned long long*>(&v);
    }
    __syncthreads();

    int ty = tid >> 4, tx = tid & 15;

    unsigned long long acc[4][2];
    {
        unsigned long long bi = dup_f32(sb2);
        #pragma unroll
        for (int r = 0; r < 4; r++) { acc[r][0] = bi; acc[r][1] = bi; }
    }

    #pragma unroll 8
    for (int k = 0; k < HD; k++) {
        unsigned long long w2  = sw2d[k];                       // LDS.64 bcast
        unsigned long long b0  = sm.pair.Bs2[(k << 5) + tx];      // (4tx, 4tx+1)
        unsigned long long b1v = sm.pair.Bs2[(k << 5) + 16 + tx]; // (4tx+2, 4tx+3)
        const unsigned long long* Ak = &sm.pair.As_dup[(k << 6) + (ty << 2)];
        #pragma unroll
        for (int r = 0; r < 4; r++) {
            unsigned long long a2 = Ak[r];
            pair_step(acc[r][0], a2, b0, w2);
            pair_step(acc[r][1], a2, b1v, w2);
        }
    }

    // sigmoid epilogue
    float p[4][4];
    #pragma unroll
    for (int r = 0; r < 4; r++)
        #pragma unroll
        for (int cp = 0; cp < 2; cp++) {
            float lo, hi;
            asm("mov.b64 {%0, %1}, %2;" : "=f"(lo), "=f"(hi) : "l"(acc[r][cp]));
            p[r][cp * 2 + 0] = 1.0f / (1.0f + __expf(-lo));
            p[r][cp * 2 + 1] = 1.0f / (1.0f + __expf(-hi));
        }

    int i0 = ti * 64 + ty * 4;
    int j0 = tj * 64 + tx * 4;
    float* outb = out + (size_t)b * N_ * N_;

    if (ti != tj) {
        #pragma unroll
        for (int r = 0; r < 4; r++) {
            float4 v = make_float4(p[r][0], p[r][1], p[r][2], p[r][3]);
            *reinterpret_cast<float4*>(outb + (size_t)(i0 + r) * N_ + j0) = v;
        }
        #pragma unroll
        for (int c = 0; c < 4; c++) {
            float4 v = make_float4(p[0][c], p[1][c], p[2][c], p[3][c]);
            *reinterpret_cast<float4*>(outb + (size_t)(j0 + c) * N_ + i0) = v;
        }
    } else {
        #pragma unroll
        for (int r = 0; r < 4; r++)
            #pragma unroll
            for (int c = 0; c < 4; c++) {
                int i = i0 + r, j = j0 + c;
                if (i < j) {
                    float v = p[r][c];
                    outb[(size_t)i * N_ + j] = v;
                    outb[(size_t)j * N_ + i] = v;
                } else if (i == j) {
                    outb[(size_t)i * N_ + j] = 0.0f;
                }
            }
    }
}

extern "C" void kernel_launch(void* const* d_in, const int* in_sizes, int n_in,
                              void* d_out, int out_size)
{
    const float* H  = (const float*)d_in[0];   // node_emb [8192, 32]
    const float* W1 = (const float*)d_in[1];   // [64, 64]
    const float* b1 = (const float*)d_in[2];   // [64]
    const float* W2 = (const float*)d_in[3];   // [64]
    const float* b2 = (const float*)d_in[4];   // [1]
    float* out = (float*)d_out;                // [16, 512, 512]

    fused_kernel<<<576, 256>>>(H, W1, b1, W2, b2, out);
}

// round 12
// speedup vs baseline: 1.2111x; 1.2111x over previous
#include <cuda_runtime.h>
#include <cuda_fp16.h>

#define B_  16
#define N_  512
#define E_  32
#define HD  64

// Scratch (fp16): A[b][k][n] = H[b,n,:] @ W1[:32, k]
//                 Bm[b][k][n] = H[b,n,:] @ W1[32:, k] + b1[k]
__device__ __half g_A[B_ * HD * N_];
__device__ __half g_Bm[B_ * HD * N_];

// Monotonic grid-barrier counter (never reset; each call adds exactly 576,
// calls are stream-serialized -> replay-safe).
__device__ unsigned long long g_bar = 0ULL;

// ---------------------------------------------------------------------------
// smem union: phase-1 scratch overlaps the phase-2 fp16 tiles.
// pair = 16KB + 8KB = 24KB; pre = 12.4KB. 4 blocks/SM guaranteed.
// ---------------------------------------------------------------------------
struct SmemPre  { float sW[E_ * 32]; float sH[64 * 33]; };
struct SmemPair { __half2 As_dup[HD * 64];   // 16 KB  [k][i] = (a_i, a_i)
                  __half2 Bs2[HD * 32]; };   //  8 KB  [k][pos] = (b_2j, b_2j+1)
union  SmemU    { SmemPre pre; SmemPair pair; };

// ---------------------------------------------------------------------------
// Fused kernel: precompute (blocks 0..511) -> grid barrier -> fp16 pair MLP.
// ---------------------------------------------------------------------------
__global__ void __launch_bounds__(256, 4) fused_kernel(
    const float* __restrict__ H,
    const float* __restrict__ W1,
    const float* __restrict__ b1,
    const float* __restrict__ W2,
    const float* __restrict__ b2g,
    float* __restrict__ out)
{
    __shared__ SmemU sm;
    __shared__ __half2 sw2h[HD];
    __shared__ float sb2;

    int tid = threadIdx.x;
    int bid = blockIdx.x;

    // weights prolog (disjoint smem region)
    if (tid < HD) sw2h[tid] = __float2half2_rn(W2[tid]);
    if (tid == 0) sb2 = b2g[0];

    // ---- phase 1: precompute chunk in fp32, store fp16 ----
    if (bid < 512) {
        int khalf  = bid & 1;
        int which  = (bid >> 1) & 1;
        int nChunk = (bid >> 2) & 7;
        int pb     = bid >> 5;

        const float* Wsrc = W1 + which * E_ * HD + khalf * 32;
        #pragma unroll
        for (int p = tid; p < E_ * 32; p += 256) {
            int r = p >> 5, c = p & 31;
            sm.pre.sW[p] = Wsrc[r * HD + c];
        }
        int nBase = pb * N_ + nChunk * 64;
        #pragma unroll
        for (int p = tid; p < 64 * E_; p += 256) {
            int r = p >> 5, c = p & 31;
            sm.pre.sH[r * 33 + c] = H[nBase * E_ + p];
        }
        __syncthreads();

        int nL   = tid & 63;
        int kOff = (tid >> 6) * 8;

        float h[E_];
        #pragma unroll
        for (int e = 0; e < E_; e++) h[e] = sm.pre.sH[nL * 33 + e];

        __half* dst = which ? g_Bm : g_A;
        #pragma unroll
        for (int kk = 0; kk < 8; kk++) {
            int kq = kOff + kk;
            int k  = khalf * 32 + kq;
            float acc = which ? b1[k] : 0.0f;
            #pragma unroll
            for (int e = 0; e < E_; e++)
                acc = fmaf(h[e], sm.pre.sW[e * 32 + kq], acc);
            dst[(pb * HD + k) * N_ + nChunk * 64 + nL] = __float2half(acc);
        }
    }

    // ---- grid barrier (all 576 blocks co-resident: 4/SM x 148 = 592) ----
    __syncthreads();
    if (tid == 0) {
        __threadfence();
        unsigned long long old = atomicAdd(&g_bar, 1ULL);
        unsigned long long target = (old / 576ULL + 1ULL) * 576ULL;
        while (*(volatile unsigned long long*)&g_bar < target) { }
        __threadfence();
    }
    __syncthreads();

    // ---- phase 2: fp16 pair MLP over 64x64 upper-triangle tiles ----
    int b = bid & 15;
    int t = bid >> 4;
    int ti = 0;
    while (t >= (8 - ti)) { t -= (8 - ti); ti++; }
    int tj = ti + t;    // ti <= tj

    // Fill As_dup: each a duplicated into a half2
    const __half* Ag = g_A + (size_t)b * HD * N_ + ti * 64;
    #pragma unroll
    for (int p = 0; p < 8; p++) {
        int idx = tid + p * 256;          // 0..2047
        int k = idx >> 5, ip = idx & 31;  // ip = half2 index within 64-row
        __half2 v = *(reinterpret_cast<const __half2*>(Ag + (size_t)k * N_) + ip);
        sm.pair.As_dup[(k << 6) + (ip << 1) + 0] = __half2half2(__low2half(v));
        sm.pair.As_dup[(k << 6) + (ip << 1) + 1] = __half2half2(__high2half(v));
    }
    // Fill Bs2: natural adjacent-j half2 pairs, interleaved (jp&1)*16 + jp>>1
    const __half* Bg = g_Bm + (size_t)b * HD * N_ + tj * 64;
    #pragma unroll
    for (int p = 0; p < 8; p++) {
        int idx = tid + p * 256;          // 0..2047
        int k = idx >> 5, jp = idx & 31;
        __half2 v = *(reinterpret_cast<const __half2*>(Bg + (size_t)k * N_) + jp);
        int pos = ((jp & 1) << 4) | (jp >> 1);
        sm.pair.Bs2[(k << 5) + pos] = v;
    }
    __syncthreads();

    int ty = tid >> 4, tx = tid & 15;

    // even/odd-k split accumulators (halves the fp16 accumulation chain)
    __half2 acc[4][2][2];
    #pragma unroll
    for (int r = 0; r < 4; r++)
        #pragma unroll
        for (int c = 0; c < 2; c++) {
            acc[r][c][0] = __float2half2_rn(0.0f);
            acc[r][c][1] = __float2half2_rn(0.0f);
        }

    const __half2 hzero = __float2half2_rn(0.0f);
    const float4* Arow = reinterpret_cast<const float4*>(sm.pair.As_dup + (ty << 2));

    #pragma unroll 16
    for (int k = 0; k < HD; k++) {
        __half2 w2 = sw2h[k];                           // LDS.32 bcast
        __half2 b0 = sm.pair.Bs2[(k << 5) + tx];        // (b_4tx,   b_4tx+1)
        __half2 b1v = sm.pair.Bs2[(k << 5) + 16 + tx];  // (b_4tx+2, b_4tx+3)
        // one LDS.128: 4 duplicated A half2s for rows ty*4..ty*4+3
        float4 araw = Arow[k << 4];                     // row stride 64 half2 = 16 float4
        __half2 a[4];
        a[0] = *reinterpret_cast<__half2*>(&araw.x);
        a[1] = *reinterpret_cast<__half2*>(&araw.y);
        a[2] = *reinterpret_cast<__half2*>(&araw.z);
        a[3] = *reinterpret_cast<__half2*>(&araw.w);
        int par = k & 1;
        #pragma unroll
        for (int r = 0; r < 4; r++) {
            __half2 t0 = __hmax2(__hadd2(a[r], b0),  hzero);
            acc[r][0][par] = __hfma2(t0, w2, acc[r][0][par]);
            __half2 t1 = __hmax2(__hadd2(a[r], b1v), hzero);
            acc[r][1][par] = __hfma2(t1, w2, acc[r][1][par]);
        }
    }

    // combine even/odd in fp32, add bias, sigmoid
    float p[4][4];
    #pragma unroll
    for (int r = 0; r < 4; r++)
        #pragma unroll
        for (int c = 0; c < 2; c++) {
            float2 fe = __half22float2(acc[r][c][0]);
            float2 fo = __half22float2(acc[r][c][1]);
            float l0 = fe.x + fo.x + sb2;
            float l1 = fe.y + fo.y + sb2;
            p[r][c * 2 + 0] = 1.0f / (1.0f + __expf(-l0));
            p[r][c * 2 + 1] = 1.0f / (1.0f + __expf(-l1));
        }

    int i0 = ti * 64 + ty * 4;
    int j0 = tj * 64 + tx * 4;
    float* outb = out + (size_t)b * N_ * N_;

    if (ti != tj) {
        #pragma unroll
        for (int r = 0; r < 4; r++) {
            float4 v = make_float4(p[r][0], p[r][1], p[r][2], p[r][3]);
            *reinterpret_cast<float4*>(outb + (size_t)(i0 + r) * N_ + j0) = v;
        }
        #pragma unroll
        for (int c = 0; c < 4; c++) {
            float4 v = make_float4(p[0][c], p[1][c], p[2][c], p[3][c]);
            *reinterpret_cast<float4*>(outb + (size_t)(j0 + c) * N_ + i0) = v;
        }
    } else {
        #pragma unroll
        for (int r = 0; r < 4; r++)
            #pragma unroll
            for (int c = 0; c < 4; c++) {
                int i = i0 + r, j = j0 + c;
                if (i < j) {
                    float v = p[r][c];
                    outb[(size_t)i * N_ + j] = v;
                    outb[(size_t)j * N_ + i] = v;
                } else if (i == j) {
                    outb[(size_t)i * N_ + j] = 0.0f;
                }
            }
    }
}

extern "C" void kernel_launch(void* const* d_in, const int* in_sizes, int n_in,
                              void* d_out, int out_size)
{
    const float* H  = (const float*)d_in[0];   // node_emb [8192, 32]
    const float* W1 = (const float*)d_in[1];   // [64, 64]
    const float* b1 = (const float*)d_in[2];   // [64]
    const float* W2 = (const float*)d_in[3];   // [64]
    const float* b2 = (const float*)d_in[4];   // [1]
    float* out = (float*)d_out;                // [16, 512, 512]

    fused_kernel<<<576, 256>>>(H, W1, b1, W2, b2, out);
}

// round 13
// speedup vs baseline: 1.2314x; 1.0168x over previous
#include <cuda_runtime.h>
#include <cuda_fp16.h>

#define B_  16
#define N_  512
#define E_  32
#define HD  64

// Scratch (fp16): A[b][k][n] = H[b,n,:] @ W1[:32, k]
//                 Bm[b][k][n] = H[b,n,:] @ W1[32:, k] + b1[k]
__device__ __half g_A[B_ * HD * N_];
__device__ __half g_Bm[B_ * HD * N_];

// Monotonic grid-barrier counter (never reset; each call adds exactly 576,
// calls are stream-serialized -> replay-safe).
__device__ unsigned long long g_bar = 0ULL;

// ---------------------------------------------------------------------------
// smem union: phase-1 scratch overlaps the phase-2 fp16 tiles.
// pair = 16KB + 8KB = 24KB; pre = 12.4KB. 4 blocks/SM guaranteed by regs.
// ---------------------------------------------------------------------------
struct SmemPre  { float sW[E_ * 32]; float sH[64 * 33]; };
struct SmemPair { __half2 As_dup[HD * 64];   // 16 KB  [k][i] = (a_i, a_i)
                  __half2 Bs2[HD * 32]; };   //  8 KB  [k][jp] natural order
union  SmemU    { SmemPre pre; SmemPair pair; };

// ---------------------------------------------------------------------------
// Fused kernel: precompute (blocks 0..511) -> grid barrier -> fp16 pair MLP.
// ---------------------------------------------------------------------------
__global__ void __launch_bounds__(256, 4) fused_kernel(
    const float* __restrict__ H,
    const float* __restrict__ W1,
    const float* __restrict__ b1,
    const float* __restrict__ W2,
    const float* __restrict__ b2g,
    float* __restrict__ out)
{
    __shared__ SmemU sm;
    __shared__ __half2 sw2h[HD];
    __shared__ float sb2;

    int tid = threadIdx.x;
    int bid = blockIdx.x;

    // weights prolog (disjoint smem region)
    if (tid < HD) sw2h[tid] = __float2half2_rn(W2[tid]);
    if (tid == 0) sb2 = b2g[0];

    // ---- phase 1: precompute chunk in fp32, store fp16 ----
    if (bid < 512) {
        int khalf  = bid & 1;
        int which  = (bid >> 1) & 1;
        int nChunk = (bid >> 2) & 7;
        int pb     = bid >> 5;

        const float* Wsrc = W1 + which * E_ * HD + khalf * 32;
        #pragma unroll
        for (int p = tid; p < E_ * 32; p += 256) {
            int r = p >> 5, c = p & 31;
            sm.pre.sW[p] = Wsrc[r * HD + c];
        }
        int nBase = pb * N_ + nChunk * 64;
        #pragma unroll
        for (int p = tid; p < 64 * E_; p += 256) {
            int r = p >> 5, c = p & 31;
            sm.pre.sH[r * 33 + c] = H[nBase * E_ + p];
        }
        __syncthreads();

        int nL   = tid & 63;
        int kOff = (tid >> 6) * 8;

        float h[E_];
        #pragma unroll
        for (int e = 0; e < E_; e++) h[e] = sm.pre.sH[nL * 33 + e];

        __half* dst = which ? g_Bm : g_A;
        #pragma unroll
        for (int kk = 0; kk < 8; kk++) {
            int kq = kOff + kk;
            int k  = khalf * 32 + kq;
            float acc = which ? b1[k] : 0.0f;
            #pragma unroll
            for (int e = 0; e < E_; e++)
                acc = fmaf(h[e], sm.pre.sW[e * 32 + kq], acc);
            dst[(pb * HD + k) * N_ + nChunk * 64 + nL] = __float2half(acc);
        }
    }

    // ---- grid barrier (all 576 blocks co-resident: 4/SM x 148 = 592) ----
    __syncthreads();
    if (tid == 0) {
        __threadfence();
        unsigned long long old = atomicAdd(&g_bar, 1ULL);
        unsigned long long target = (old / 576ULL + 1ULL) * 576ULL;
        while (*(volatile unsigned long long*)&g_bar < target) { }
        __threadfence();
    }
    __syncthreads();

    // ---- phase 2: fp16 pair MLP over 64x64 upper-triangle tiles ----
    int b = bid & 15;
    int t = bid >> 4;
    int ti = 0;
    while (t >= (8 - ti)) { t -= (8 - ti); ti++; }
    int tj = ti + t;    // ti <= tj

    // Fill As_dup: each a duplicated into a half2
    const __half* Ag = g_A + (size_t)b * HD * N_ + ti * 64;
    #pragma unroll
    for (int p = 0; p < 8; p++) {
        int idx = tid + p * 256;          // 0..2047
        int k = idx >> 5, ip = idx & 31;  // ip = half2 index within 64-row
        __half2 v = *(reinterpret_cast<const __half2*>(Ag + (size_t)k * N_) + ip);
        sm.pair.As_dup[(k << 6) + (ip << 1) + 0] = __half2half2(__low2half(v));
        sm.pair.As_dup[(k << 6) + (ip << 1) + 1] = __half2half2(__high2half(v));
    }
    // Fill Bs2: natural adjacent-j half2 pairs (jp in order -> the two pairs a
    // thread needs are adjacent => single LDS.64 in the loop)
    const __half* Bg = g_Bm + (size_t)b * HD * N_ + tj * 64;
    #pragma unroll
    for (int p = 0; p < 8; p++) {
        int idx = tid + p * 256;          // 0..2047
        int k = idx >> 5, jp = idx & 31;
        sm.pair.Bs2[(k << 5) + jp] = *(reinterpret_cast<const __half2*>(Bg + (size_t)k * N_) + jp);
    }
    __syncthreads();

    int ty = tid >> 4, tx = tid & 15;

    __half2 acc[4][2];
    #pragma unroll
    for (int r = 0; r < 4; r++) {
        acc[r][0] = __float2half2_rn(0.0f);
        acc[r][1] = __float2half2_rn(0.0f);
    }

    const __half2 hzero = __float2half2_rn(0.0f);
    const float4* Arow = reinterpret_cast<const float4*>(sm.pair.As_dup + (ty << 2));
    const unsigned long long* Brow =
        reinterpret_cast<const unsigned long long*>(sm.pair.Bs2 + (tx << 1));

    #pragma unroll 8
    for (int k = 0; k < HD; k++) {
        __half2 w2 = sw2h[k];                          // LDS.32 bcast
        unsigned long long braw = Brow[k << 4];        // LDS.64: (b_4tx..b_4tx+3)
        float4 araw = Arow[k << 4];                    // LDS.128: 4 dup'd A half2
        __half2 b0 = *reinterpret_cast<__half2*>(&braw);
        __half2 b1v = *(reinterpret_cast<__half2*>(&braw) + 1);
        __half2 a[4];
        a[0] = *reinterpret_cast<__half2*>(&araw.x);
        a[1] = *reinterpret_cast<__half2*>(&araw.y);
        a[2] = *reinterpret_cast<__half2*>(&araw.z);
        a[3] = *reinterpret_cast<__half2*>(&araw.w);
        #pragma unroll
        for (int r = 0; r < 4; r++) {
            __half2 t0 = __hmax2(__hadd2(a[r], b0),  hzero);
            acc[r][0] = __hfma2(t0, w2, acc[r][0]);
            __half2 t1 = __hmax2(__hadd2(a[r], b1v), hzero);
            acc[r][1] = __hfma2(t1, w2, acc[r][1]);
        }
    }

    // fp32 bias + sigmoid epilogue
    float p[4][4];
    #pragma unroll
    for (int r = 0; r < 4; r++)
        #pragma unroll
        for (int c = 0; c < 2; c++) {
            float2 f = __half22float2(acc[r][c]);
            p[r][c * 2 + 0] = 1.0f / (1.0f + __expf(-(f.x + sb2)));
            p[r][c * 2 + 1] = 1.0f / (1.0f + __expf(-(f.y + sb2)));
        }

    int i0 = ti * 64 + ty * 4;
    int j0 = tj * 64 + tx * 4;
    float* outb = out + (size_t)b * N_ * N_;

    if (ti != tj) {
        #pragma unroll
        for (int r = 0; r < 4; r++) {
            float4 v = make_float4(p[r][0], p[r][1], p[r][2], p[r][3]);
            *reinterpret_cast<float4*>(outb + (size_t)(i0 + r) * N_ + j0) = v;
        }
        #pragma unroll
        for (int c = 0; c < 4; c++) {
            float4 v = make_float4(p[0][c], p[1][c], p[2][c], p[3][c]);
            *reinterpret_cast<float4*>(outb + (size_t)(j0 + c) * N_ + i0) = v;
        }
    } else {
        #pragma unroll
        for (int r = 0; r < 4; r++)
            #pragma unroll
            for (int c = 0; c < 4; c++) {
                int i = i0 + r, j = j0 + c;
                if (i < j) {
                    float v = p[r][c];
                    outb[(size_t)i * N_ + j] = v;
                    outb[(size_t)j * N_ + i] = v;
                } else if (i == j) {
                    outb[(size_t)i * N_ + j] = 0.0f;
                }
            }
    }
}

extern "C" void kernel_launch(void* const* d_in, const int* in_sizes, int n_in,
                              void* d_out, int out_size)
{
    const float* H  = (const float*)d_in[0];   // node_emb [8192, 32]
    const float* W1 = (const float*)d_in[1];   // [64, 64]
    const float* b1 = (const float*)d_in[2];   // [64]
    const float* W2 = (const float*)d_in[3];   // [64]
    const float* b2 = (const float*)d_in[4];   // [1]
    float* out = (float*)d_out;                // [16, 512, 512]

    fused_kernel<<<576, 256>>>(H, W1, b1, W2, b2, out);
}

// round 14
// speedup vs baseline: 1.3116x; 1.0651x over previous
#include <cuda_runtime.h>
#include <cuda_fp16.h>

#define B_  16
#define N_  512
#define E_  32
#define HD  64

// Scratch (fp16): A[b][k][n] = H[b,n,:] @ W1[:32, k]
//                 Bm[b][k][n] = H[b,n,:] @ W1[32:, k] + b1[k]
__device__ __half g_A[B_ * HD * N_];
__device__ __half g_Bm[B_ * HD * N_];

// Monotonic grid-barrier counter (never reset; each call adds exactly 576,
// calls are stream-serialized -> replay-safe).
__device__ unsigned long long g_bar = 0ULL;

// ---------------------------------------------------------------------------
// smem union: phase-1 scratch overlaps the phase-2 fp16 tiles.
// pair = 16KB + 8KB = 24KB; pre = 12.4KB. 4 blocks/SM.
// ---------------------------------------------------------------------------
struct SmemPre  { float sW[E_ * 32]; float sH[64 * 33]; };
struct SmemPair { __half2 As_dup[HD * 64];   // 16 KB  [k][i] = (a_i, a_i)
                  __half2 Bs2[HD * 32]; };   //  8 KB  [k][jp] natural order
union  SmemU    { SmemPre pre; SmemPair pair; };

// ---------------------------------------------------------------------------
// Fused kernel: precompute (blocks 0..511) -> grid barrier -> fp16 pair MLP.
// ---------------------------------------------------------------------------
__global__ void __launch_bounds__(256, 4) fused_kernel(
    const float* __restrict__ H,
    const float* __restrict__ W1,
    const float* __restrict__ b1,
    const float* __restrict__ W2,
    const float* __restrict__ b2g,
    float* __restrict__ out)
{
    __shared__ SmemU sm;
    __shared__ __half2 sw2h[HD];
    __shared__ float sb2;

    int tid = threadIdx.x;
    int bid = blockIdx.x;

    // weights prolog (disjoint smem region)
    if (tid < HD) sw2h[tid] = __float2half2_rn(W2[tid]);
    if (tid == 0) sb2 = b2g[0];

    // ---- phase 1: precompute chunk in fp32, store fp16 ----
    if (bid < 512) {
        int khalf  = bid & 1;
        int which  = (bid >> 1) & 1;
        int nChunk = (bid >> 2) & 7;
        int pb     = bid >> 5;

        const float* Wsrc = W1 + which * E_ * HD + khalf * 32;
        #pragma unroll
        for (int p = tid; p < E_ * 32; p += 256) {
            int r = p >> 5, c = p & 31;
            sm.pre.sW[p] = Wsrc[r * HD + c];
        }
        int nBase = pb * N_ + nChunk * 64;
        #pragma unroll
        for (int p = tid; p < 64 * E_; p += 256) {
            int r = p >> 5, c = p & 31;
            sm.pre.sH[r * 33 + c] = H[nBase * E_ + p];
        }
        __syncthreads();

        int nL   = tid & 63;
        int kOff = (tid >> 6) * 8;

        float h[E_];
        #pragma unroll
        for (int e = 0; e < E_; e++) h[e] = sm.pre.sH[nL * 33 + e];

        __half* dst = which ? g_Bm : g_A;
        #pragma unroll
        for (int kk = 0; kk < 8; kk++) {
            int kq = kOff + kk;
            int k  = khalf * 32 + kq;
            float acc = which ? b1[k] : 0.0f;
            #pragma unroll
            for (int e = 0; e < E_; e++)
                acc = fmaf(h[e], sm.pre.sW[e * 32 + kq], acc);
            dst[(pb * HD + k) * N_ + nChunk * 64 + nL] = __float2half(acc);
        }
    }

    // ---- grid barrier (all 576 blocks co-resident: 4/SM x 148 = 592) ----
    __syncthreads();
    if (tid == 0) {
        __threadfence();
        unsigned long long old = atomicAdd(&g_bar, 1ULL);
        unsigned long long target = (old / 576ULL + 1ULL) * 576ULL;
        while (*(volatile unsigned long long*)&g_bar < target) { }
        __threadfence();
    }
    __syncthreads();

    // ---- phase 2: fp16 pair MLP over 64x64 upper-triangle tiles ----
    int b = bid & 15;
    int t = bid >> 4;
    int ti = 0;
    while (t >= (8 - ti)) { t -= (8 - ti); ti++; }
    int tj = ti + t;    // ti <= tj

    // Fill As_dup: each a duplicated into a half2
    const __half* Ag = g_A + (size_t)b * HD * N_ + ti * 64;
    #pragma unroll
    for (int p = 0; p < 8; p++) {
        int idx = tid + p * 256;          // 0..2047
        int k = idx >> 5, ip = idx & 31;  // ip = half2 index within 64-row
        __half2 v = *(reinterpret_cast<const __half2*>(Ag + (size_t)k * N_) + ip);
        sm.pair.As_dup[(k << 6) + (ip << 1) + 0] = __half2half2(__low2half(v));
        sm.pair.As_dup[(k << 6) + (ip << 1) + 1] = __half2half2(__high2half(v));
    }
    // Fill Bs2: natural adjacent-j half2 pairs (two needed pairs adjacent =>
    // single LDS.64 in the loop)
    const __half* Bg = g_Bm + (size_t)b * HD * N_ + tj * 64;
    #pragma unroll
    for (int p = 0; p < 8; p++) {
        int idx = tid + p * 256;          // 0..2047
        int k = idx >> 5, jp = idx & 31;
        sm.pair.Bs2[(k << 5) + jp] = *(reinterpret_cast<const __half2*>(Bg + (size_t)k * N_) + jp);
    }
    __syncthreads();

    int ty = tid >> 4, tx = tid & 15;

    __half2 acc[4][2];
    #pragma unroll
    for (int r = 0; r < 4; r++) {
        acc[r][0] = __float2half2_rn(0.0f);
        acc[r][1] = __float2half2_rn(0.0f);
    }

    const __half2 hone = __float2half2_rn(1.0f);
    const float4* Arow = reinterpret_cast<const float4*>(sm.pair.As_dup + (ty << 2));
    const unsigned long long* Brow =
        reinterpret_cast<const unsigned long long*>(sm.pair.Bs2 + (tx << 1));

    #pragma unroll 8
    for (int k = 0; k < HD; k++) {
        __half2 w2 = sw2h[k];                          // LDS.32 bcast
        unsigned long long braw = Brow[k << 4];        // LDS.64: (b_4tx..b_4tx+3)
        float4 araw = Arow[k << 4];                    // LDS.128: 4 dup'd A half2
        __half2 b0 = *reinterpret_cast<__half2*>(&braw);
        __half2 b1v = *(reinterpret_cast<__half2*>(&braw) + 1);
        __half2 a[4];
        a[0] = *reinterpret_cast<__half2*>(&araw.x);
        a[1] = *reinterpret_cast<__half2*>(&araw.y);
        a[2] = *reinterpret_cast<__half2*>(&araw.z);
        a[3] = *reinterpret_cast<__half2*>(&araw.w);
        #pragma unroll
        for (int r = 0; r < 4; r++) {
            // relu(a+b) in ONE instruction: HFMA2.RELU (a*1 + b, clamped at 0)
            __half2 t0 = __hfma2_relu(a[r], hone, b0);
            acc[r][0] = __hfma2(t0, w2, acc[r][0]);
            __half2 t1 = __hfma2_relu(a[r], hone, b1v);
            acc[r][1] = __hfma2(t1, w2, acc[r][1]);
        }
    }

    // fp32 bias + sigmoid epilogue
    float p[4][4];
    #pragma unroll
    for (int r = 0; r < 4; r++)
        #pragma unroll
        for (int c = 0; c < 2; c++) {
            float2 f = __half22float2(acc[r][c]);
            p[r][c * 2 + 0] = 1.0f / (1.0f + __expf(-(f.x + sb2)));
            p[r][c * 2 + 1] = 1.0f / (1.0f + __expf(-(f.y + sb2)));
        }

    int i0 = ti * 64 + ty * 4;
    int j0 = tj * 64 + tx * 4;
    float* outb = out + (size_t)b * N_ * N_;

    if (ti != tj) {
        #pragma unroll
        for (int r = 0; r < 4; r++) {
            float4 v = make_float4(p[r][0], p[r][1], p[r][2], p[r][3]);
            *reinterpret_cast<float4*>(outb + (size_t)(i0 + r) * N_ + j0) = v;
        }
        #pragma unroll
        for (int c = 0; c < 4; c++) {
            float4 v = make_float4(p[0][c], p[1][c], p[2][c], p[3][c]);
            *reinterpret_cast<float4*>(outb + (size_t)(j0 + c) * N_ + i0) = v;
        }
    } else {
        #pragma unroll
        for (int r = 0; r < 4; r++)
            #pragma unroll
            for (int c = 0; c < 4; c++) {
                int i = i0 + r, j = j0 + c;
                if (i < j) {
                    float v = p[r][c];
                    outb[(size_t)i * N_ + j] = v;
                    outb[(size_t)j * N_ + i] = v;
                } else if (i == j) {
                    outb[(size_t)i * N_ + j] = 0.0f;
                }
            }
    }
}

extern "C" void kernel_launch(void* const* d_in, const int* in_sizes, int n_in,
                              void* d_out, int out_size)
{
    const float* H  = (const float*)d_in[0];   // node_emb [8192, 32]
    const float* W1 = (const float*)d_in[1];   // [64, 64]
    const float* b1 = (const float*)d_in[2];   // [64]
    const float* W2 = (const float*)d_in[3];   // [64]
    const float* b2 = (const float*)d_in[4];   // [1]
    float* out = (float*)d_out;                // [16, 512, 512]

    fused_kernel<<<576, 256>>>(H, W1, b1, W2, b2, out);
}

// round 15
// speedup vs baseline: 1.3150x; 1.0026x over previous
#include <cuda_runtime.h>
#include <cuda_fp16.h>

#define B_  16
#define N_  512
#define E_  32
#define HD  64

// Scratch (fp16)
__device__ __half g_A[B_ * HD * N_];
__device__ __half g_Bm[B_ * HD * N_];

// Monotonic grid-barrier counter (replay-safe: each call adds exactly 576).
__device__ unsigned long long g_bar = 0ULL;

struct SmemPre  { float sW[E_ * 32]; float sH[64 * 33]; };
struct SmemPair { __half2 As_dup[HD * 64];   // 16 KB [k][i] = (a_i, a_i)
                  __half2 Bs2[HD * 32]; };   //  8 KB [k][jp] natural
union  SmemU    { SmemPre pre; SmemPair pair; };

__global__ void __launch_bounds__(256, 6) fused_kernel(
    const float* __restrict__ H,
    const float* __restrict__ W1,
    const float* __restrict__ b1,
    const float* __restrict__ W2,
    const float* __restrict__ b2g,
    float* __restrict__ out)
{
    __shared__ SmemU sm;
    __shared__ alignas(16) __half2 sw2h[HD];
    __shared__ float sb2;

    int tid = threadIdx.x;
    int bid = blockIdx.x;

    if (tid < HD) sw2h[tid] = __float2half2_rn(W2[tid]);
    if (tid == 0) sb2 = b2g[0];

    // ---- phase 1: precompute chunk (low-register 2-pass form) ----
    if (bid < 512) {
        int khalf  = bid & 1;
        int which  = (bid >> 1) & 1;
        int nChunk = (bid >> 2) & 7;
        int pb     = bid >> 5;

        const float* Wsrc = W1 + which * E_ * HD + khalf * 32;
        #pragma unroll
        for (int p = tid; p < E_ * 32; p += 256) {
            int r = p >> 5, c = p & 31;
            sm.pre.sW[p] = Wsrc[r * HD + c];
        }
        int nBase = pb * N_ + nChunk * 64;
        #pragma unroll
        for (int p = tid; p < 64 * E_; p += 256) {
            int r = p >> 5, c = p & 31;
            sm.pre.sH[r * 33 + c] = H[nBase * E_ + p];
        }
        __syncthreads();

        int nL   = tid & 63;
        int kOff = (tid >> 6) * 8;

        float accv[8];
        #pragma unroll
        for (int kk = 0; kk < 8; kk++)
            accv[kk] = which ? b1[khalf * 32 + kOff + kk] : 0.0f;

        // pass 1: e = 0..15
        {
            float h0[16];
            #pragma unroll
            for (int e = 0; e < 16; e++) h0[e] = sm.pre.sH[nL * 33 + e];
            #pragma unroll
            for (int e = 0; e < 16; e++)
                #pragma unroll
                for (int kk = 0; kk < 8; kk++)
                    accv[kk] = fmaf(h0[e], sm.pre.sW[e * 32 + kOff + kk], accv[kk]);
        }
        // pass 2: e = 16..31
        {
            float h0[16];
            #pragma unroll
            for (int e = 0; e < 16; e++) h0[e] = sm.pre.sH[nL * 33 + 16 + e];
            #pragma unroll
            for (int e = 0; e < 16; e++)
                #pragma unroll
                for (int kk = 0; kk < 8; kk++)
                    accv[kk] = fmaf(h0[e], sm.pre.sW[(16 + e) * 32 + kOff + kk], accv[kk]);
        }

        __half* dst = which ? g_Bm : g_A;
        #pragma unroll
        for (int kk = 0; kk < 8; kk++) {
            int k = khalf * 32 + kOff + kk;
            dst[(pb * HD + k) * N_ + nChunk * 64 + nL] = __float2half(accv[kk]);
        }
    }

    // ---- grid barrier (576 <= 6*148 = 888 co-resident slots) ----
    __syncthreads();
    if (tid == 0) {
        __threadfence();
        unsigned long long old = atomicAdd(&g_bar, 1ULL);
        unsigned long long target = (old / 576ULL + 1ULL) * 576ULL;
        while (*(volatile unsigned long long*)&g_bar < target) { }
        __threadfence();
    }
    __syncthreads();

    // ---- phase 2: fp16 pair MLP, 64x64 upper-triangle tiles ----
    int b = bid & 15;
    int t = bid >> 4;
    int ti = 0;
    while (t >= (8 - ti)) { t -= (8 - ti); ti++; }
    int tj = ti + t;    // ti <= tj

    const __half* Ag = g_A + (size_t)b * HD * N_ + ti * 64;
    #pragma unroll
    for (int p = 0; p < 8; p++) {
        int idx = tid + p * 256;
        int k = idx >> 5, ip = idx & 31;
        __half2 v = *(reinterpret_cast<const __half2*>(Ag + (size_t)k * N_) + ip);
        sm.pair.As_dup[(k << 6) + (ip << 1) + 0] = __half2half2(__low2half(v));
        sm.pair.As_dup[(k << 6) + (ip << 1) + 1] = __half2half2(__high2half(v));
    }
    const __half* Bg = g_Bm + (size_t)b * HD * N_ + tj * 64;
    #pragma unroll
    for (int p = 0; p < 8; p++) {
        int idx = tid + p * 256;
        int k = idx >> 5, jp = idx & 31;
        sm.pair.Bs2[(k << 5) + jp] = *(reinterpret_cast<const __half2*>(Bg + (size_t)k * N_) + jp);
    }
    __syncthreads();

    int ty = tid >> 4, tx = tid & 15;

    __half2 acc[4][2];
    #pragma unroll
    for (int r = 0; r < 4; r++) {
        acc[r][0] = __float2half2_rn(0.0f);
        acc[r][1] = __float2half2_rn(0.0f);
    }

    const __half2 hone = __float2half2_rn(1.0f);
    const float4* Arow = reinterpret_cast<const float4*>(sm.pair.As_dup + (ty << 2));
    const unsigned long long* Brow =
        reinterpret_cast<const unsigned long long*>(sm.pair.Bs2 + (tx << 1));
    const float4* W2f4 = reinterpret_cast<const float4*>(sw2h);

    #pragma unroll
    for (int kc = 0; kc < 8; kc++) {              // 8 chunks of 8 k
        // w2 chunk: 2x LDS.128 (8 half2)
        float4 wraw0 = W2f4[kc * 2 + 0];
        float4 wraw1 = W2f4[kc * 2 + 1];
        __half2 w2c[8];
        w2c[0] = *reinterpret_cast<__half2*>(&wraw0.x);
        w2c[1] = *reinterpret_cast<__half2*>(&wraw0.y);
        w2c[2] = *reinterpret_cast<__half2*>(&wraw0.z);
        w2c[3] = *reinterpret_cast<__half2*>(&wraw0.w);
        w2c[4] = *reinterpret_cast<__half2*>(&wraw1.x);
        w2c[5] = *reinterpret_cast<__half2*>(&wraw1.y);
        w2c[6] = *reinterpret_cast<__half2*>(&wraw1.z);
        w2c[7] = *reinterpret_cast<__half2*>(&wraw1.w);

        #pragma unroll
        for (int kk = 0; kk < 8; kk++) {
            int k = kc * 8 + kk;
            unsigned long long braw = Brow[k << 4];   // LDS.64
            float4 araw = Arow[k << 4];               // LDS.128 (bcast)
            __half2 b0 = *reinterpret_cast<__half2*>(&braw);
            __half2 b1v = *(reinterpret_cast<__half2*>(&braw) + 1);
            __half2 a[4];
            a[0] = *reinterpret_cast<__half2*>(&araw.x);
            a[1] = *reinterpret_cast<__half2*>(&araw.y);
            a[2] = *reinterpret_cast<__half2*>(&araw.z);
            a[3] = *reinterpret_cast<__half2*>(&araw.w);
            #pragma unroll
            for (int r = 0; r < 4; r++) {
                __half2 t0 = __hfma2_relu(a[r], hone, b0);
                acc[r][0] = __hfma2(t0, w2c[kk], acc[r][0]);
                __half2 t1 = __hfma2_relu(a[r], hone, b1v);
                acc[r][1] = __hfma2(t1, w2c[kk], acc[r][1]);
            }
        }
    }

    // fp32 bias + sigmoid epilogue
    float p[4][4];
    #pragma unroll
    for (int r = 0; r < 4; r++)
        #pragma unroll
        for (int c = 0; c < 2; c++) {
            float2 f = __half22float2(acc[r][c]);
            p[r][c * 2 + 0] = 1.0f / (1.0f + __expf(-(f.x + sb2)));
            p[r][c * 2 + 1] = 1.0f / (1.0f + __expf(-(f.y + sb2)));
        }

    int i0 = ti * 64 + ty * 4;
    int j0 = tj * 64 + tx * 4;
    float* outb = out + (size_t)b * N_ * N_;

    if (ti != tj) {
        #pragma unroll
        for (int r = 0; r < 4; r++) {
            float4 v = make_float4(p[r][0], p[r][1], p[r][2], p[r][3]);
            *reinterpret_cast<float4*>(outb + (size_t)(i0 + r) * N_ + j0) = v;
        }
        #pragma unroll
        for (int c = 0; c < 4; c++) {
            float4 v = make_float4(p[0][c], p[1][c], p[2][c], p[3][c]);
            *reinterpret_cast<float4*>(outb + (size_t)(j0 + c) * N_ + i0) = v;
        }
    } else {
        #pragma unroll
        for (int r = 0; r < 4; r++)
            #pragma unroll
            for (int c = 0; c < 4; c++) {
                int i = i0 + r, j = j0 + c;
                if (i < j) {
                    float v = p[r][c];
                    outb[(size_t)i * N_ + j] = v;
                    outb[(size_t)j * N_ + i] = v;
                } else if (i == j) {
                    outb[(size_t)i * N_ + j] = 0.0f;
                }
            }
    }
}

extern "C" void kernel_launch(void* const* d_in, const int* in_sizes, int n_in,
                              void* d_out, int out_size)
{
    const float* H  = (const float*)d_in[0];
    const float* W1 = (const float*)d_in[1];
    const float* b1 = (const float*)d_in[2];
    const float* W2 = (const float*)d_in[3];
    const float* b2 = (const float*)d_in[4];
    float* out = (float*)d_out;

    fused_kernel<<<576, 256>>>(H, W1, b1, W2, b2, out);
}

// round 16
// speedup vs baseline: 1.4146x; 1.0758x over previous
#include <cuda_runtime.h>
#include <cuda_fp16.h>

#define B_  16
#define N_  512
#define E_  32
#define HD  64

#define GRID_SIZE 1152

// Scratch (fp16)
__device__ __half g_A[B_ * HD * N_];
__device__ __half g_Bm[B_ * HD * N_];

// Replay-safe sync state (monotonic, never reset):
//  g_entry: every block adds 1 at entry -> epoch = old / GRID_SIZE
//  g_flag[which][b*8+nChunk]: each of 2 producers (khalf 0/1) adds 1
__device__ unsigned long long g_entry = 0ULL;
__device__ unsigned int g_flag[2][B_ * 8];

struct SmemPre  { float sW[E_ * 32]; float sH[64 * 33]; };   // 12.4 KB
struct SmemPair { __half2 As_dup[HD * 64];                   // 16 KB [k][i]=(a_i,a_i)
                  __half2 Bs2[HD * 16]; };                   //  4 KB [k][jp]
union  SmemU    { SmemPre pre; SmemPair pair; };

__global__ void __launch_bounds__(256, 6) fused_kernel(
    const float* __restrict__ H,
    const float* __restrict__ W1,
    const float* __restrict__ b1,
    const float* __restrict__ W2,
    const float* __restrict__ b2g,
    float* __restrict__ out)
{
    __shared__ SmemU sm;
    __shared__ alignas(16) __half2 sw2h[HD];
    __shared__ float sb2;
    __shared__ unsigned int sEpoch;

    int tid = threadIdx.x;
    int bid = blockIdx.x;

    if (tid == 0) {
        unsigned long long e = atomicAdd(&g_entry, 1ULL);
        sEpoch = (unsigned int)(e / (unsigned long long)GRID_SIZE);
        sb2 = b2g[0];
    }
    if (tid < HD) sw2h[tid] = __float2half2_rn(W2[tid]);

    // ---- phase 1: producers (blocks 0..511), low-register 2-pass form ----
    if (bid < 512) {
        int khalf  = bid & 1;
        int which  = (bid >> 1) & 1;
        int nChunk = (bid >> 2) & 7;
        int pb     = bid >> 5;

        const float* Wsrc = W1 + which * E_ * HD + khalf * 32;
        #pragma unroll
        for (int p = tid; p < E_ * 32; p += 256) {
            int r = p >> 5, c = p & 31;
            sm.pre.sW[p] = Wsrc[r * HD + c];
        }
        int nBase = pb * N_ + nChunk * 64;
        #pragma unroll
        for (int p = tid; p < 64 * E_; p += 256) {
            int r = p >> 5, c = p & 31;
            sm.pre.sH[r * 33 + c] = H[nBase * E_ + p];
        }
        __syncthreads();

        int nL   = tid & 63;
        int kOff = (tid >> 6) * 8;

        float accv[8];
        #pragma unroll
        for (int kk = 0; kk < 8; kk++)
            accv[kk] = which ? b1[khalf * 32 + kOff + kk] : 0.0f;

        {
            float h0[16];
            #pragma unroll
            for (int e = 0; e < 16; e++) h0[e] = sm.pre.sH[nL * 33 + e];
            #pragma unroll
            for (int e = 0; e < 16; e++)
                #pragma unroll
                for (int kk = 0; kk < 8; kk++)
                    accv[kk] = fmaf(h0[e], sm.pre.sW[e * 32 + kOff + kk], accv[kk]);
        }
        {
            float h0[16];
            #pragma unroll
            for (int e = 0; e < 16; e++) h0[e] = sm.pre.sH[nL * 33 + 16 + e];
            #pragma unroll
            for (int e = 0; e < 16; e++)
                #pragma unroll
                for (int kk = 0; kk < 8; kk++)
                    accv[kk] = fmaf(h0[e], sm.pre.sW[(16 + e) * 32 + kOff + kk], accv[kk]);
        }

        __half* dst = which ? g_Bm : g_A;
        #pragma unroll
        for (int kk = 0; kk < 8; kk++) {
            int k = khalf * 32 + kOff + kk;
            dst[(pb * HD + k) * N_ + nChunk * 64 + nL] = __float2half(accv[kk]);
        }

        // publish: every thread fences its own stores, then one flag add
        __threadfence();
        __syncthreads();
        if (tid == 0)
            atomicAdd(&g_flag[which][pb * 8 + nChunk], 1u);
    }

    __syncthreads();   // sEpoch visible; smem union phase boundary
    unsigned int epoch = sEpoch;

    // ---- phase 2: tile decode (72 tiles of 64x32 per batch) ----
    int t = bid;
    int b = t / 72;
    t -= b * 72;
    int ti = 0;
    while (t >= 16 - 2 * ti) { t -= 16 - 2 * ti; ti++; }
    int cj = 2 * ti + t;           // 32-col tile index, cj >= 2*ti

    // wait for the two chunks this tile needs
    if (tid == 0) {
        unsigned int tgt = 2u * (epoch + 1u);
        volatile unsigned int* fa = &g_flag[0][b * 8 + ti];
        volatile unsigned int* fb = &g_flag[1][b * 8 + (cj >> 1)];
        while (*fa < tgt) { }
        while (*fb < tgt) { }
        __threadfence();
    }
    __syncthreads();

    // Fill As_dup (rows ti*64..+63, dup'd) and Bs2 (cols cj*32..+31)
    const __half* Ag = g_A + (size_t)b * HD * N_ + ti * 64;
    #pragma unroll
    for (int p = 0; p < 8; p++) {
        int idx = tid + p * 256;          // 0..2047
        int k = idx >> 5, ip = idx & 31;
        __half2 v = *(reinterpret_cast<const __half2*>(Ag + (size_t)k * N_) + ip);
        sm.pair.As_dup[(k << 6) + (ip << 1) + 0] = __half2half2(__low2half(v));
        sm.pair.As_dup[(k << 6) + (ip << 1) + 1] = __half2half2(__high2half(v));
    }
    const __half* Bg = g_Bm + (size_t)b * HD * N_ + cj * 32;
    #pragma unroll
    for (int p = 0; p < 4; p++) {
        int idx = tid + p * 256;          // 0..1023
        int k = idx >> 4, jp = idx & 15;
        sm.pair.Bs2[(k << 4) + jp] = *(reinterpret_cast<const __half2*>(Bg + (size_t)k * N_) + jp);
    }
    __syncthreads();

    int ty = tid >> 3;   // 0..31 -> 2 rows
    int tx = tid & 7;    // 0..7  -> 4 cols

    __half2 acc[2][2];
    acc[0][0] = __float2half2_rn(0.0f); acc[0][1] = __float2half2_rn(0.0f);
    acc[1][0] = __float2half2_rn(0.0f); acc[1][1] = __float2half2_rn(0.0f);

    const __half2 hone = __float2half2_rn(1.0f);
    const unsigned long long* Aull =
        reinterpret_cast<const unsigned long long*>(sm.pair.As_dup);
    const unsigned long long* Bull =
        reinterpret_cast<const unsigned long long*>(sm.pair.Bs2);

    #pragma unroll 16
    for (int k = 0; k < HD; k++) {
        __half2 w2 = sw2h[k];                         // LDS.32 bcast
        unsigned long long araw = Aull[(k << 5) + ty];  // LDS.64: dup rows 2ty,2ty+1
        unsigned long long braw = Bull[(k << 3) + tx];  // LDS.64: cols 4tx..4tx+3
        __half2 a0 = *reinterpret_cast<__half2*>(&araw);
        __half2 a1 = *(reinterpret_cast<__half2*>(&araw) + 1);
        __half2 b0 = *reinterpret_cast<__half2*>(&braw);
        __half2 b1v = *(reinterpret_cast<__half2*>(&braw) + 1);
        __half2 t00 = __hfma2_relu(a0, hone, b0);
        acc[0][0] = __hfma2(t00, w2, acc[0][0]);
        __half2 t01 = __hfma2_relu(a0, hone, b1v);
        acc[0][1] = __hfma2(t01, w2, acc[0][1]);
        __half2 t10 = __hfma2_relu(a1, hone, b0);
        acc[1][0] = __hfma2(t10, w2, acc[1][0]);
        __half2 t11 = __hfma2_relu(a1, hone, b1v);
        acc[1][1] = __hfma2(t11, w2, acc[1][1]);
    }

    // fp32 bias + sigmoid epilogue
    float p[2][4];
    #pragma unroll
    for (int r = 0; r < 2; r++)
        #pragma unroll
        for (int c = 0; c < 2; c++) {
            float2 f = __half22float2(acc[r][c]);
            p[r][c * 2 + 0] = 1.0f / (1.0f + __expf(-(f.x + sb2)));
            p[r][c * 2 + 1] = 1.0f / (1.0f + __expf(-(f.y + sb2)));
        }

    int i0 = ti * 64 + ty * 2;
    int j0 = cj * 32 + tx * 4;
    float* outb = out + (size_t)b * N_ * N_;

    if (cj >= 2 * ti + 2) {
        // fully upper tile: 2x float4 + 4x float2 mirror
        #pragma unroll
        for (int r = 0; r < 2; r++) {
            float4 v = make_float4(p[r][0], p[r][1], p[r][2], p[r][3]);
            *reinterpret_cast<float4*>(outb + (size_t)(i0 + r) * N_ + j0) = v;
        }
        #pragma unroll
        for (int c = 0; c < 4; c++) {
            float2 v = make_float2(p[0][c], p[1][c]);
            *reinterpret_cast<float2*>(outb + (size_t)(j0 + c) * N_ + i0) = v;
        }
    } else {
        // diagonal-straddling tile
        #pragma unroll
        for (int r = 0; r < 2; r++)
            #pragma unroll
            for (int c = 0; c < 4; c++) {
                int i = i0 + r, j = j0 + c;
                if (i < j) {
                    float v = p[r][c];
                    outb[(size_t)i * N_ + j] = v;
                    outb[(size_t)j * N_ + i] = v;
                } else if (i == j) {
                    outb[(size_t)i * N_ + j] = 0.0f;
                }
            }
    }
}

extern "C" void kernel_launch(void* const* d_in, const int* in_sizes, int n_in,
                              void* d_out, int out_size)
{
    const float* H  = (const float*)d_in[0];
    const float* W1 = (const float*)d_in[1];
    const float* b1 = (const float*)d_in[2];
    const float* W2 = (const float*)d_in[3];
    const float* b2 = (const float*)d_in[4];
    float* out = (float*)d_out;

    fused_kernel<<<GRID_SIZE, 256>>>(H, W1, b1, W2, b2, out);
}